// round 4
// baseline (speedup 1.0000x reference)
#include <cuda_runtime.h>

// Problem constants
#define BB 16
#define CC 96
#define HH 128
#define WW 128
#define HWSZ (HH*WW)

typedef unsigned long long u64;

// Scratch (allocation-guard-safe: __device__ globals)
__device__ float g_flow [BB*2  *HWSZ];
__device__ float g_feat2[BB*CC *HWSZ];
__device__ float g_corr [BB*49 *HWSZ];
__device__ float g_x1   [BB*128*HWSZ];
__device__ float g_x2   [BB*64 *HWSZ];
__device__ float g_x3   [BB*32 *HWSZ];

__device__ __forceinline__ float lrelu_f(float x) { return x >= 0.f ? x : 0.1f * x; }

// ---- packed f32x2 helpers (FFMA2 path: only reachable via PTX) ------------
__device__ __forceinline__ u64 pack2(float lo, float hi) {
    u64 r; asm("mov.b64 %0, {%1, %2};" : "=l"(r) : "f"(lo), "f"(hi)); return r;
}
__device__ __forceinline__ u64 splat2(float v) {
    u64 r; asm("mov.b64 %0, {%1, %1};" : "=l"(r) : "f"(v)); return r;
}
__device__ __forceinline__ void unpack2(u64 v, float& lo, float& hi) {
    asm("mov.b64 {%0, %1}, %2;" : "=f"(lo), "=f"(hi) : "l"(v));
}
__device__ __forceinline__ void ffma2(u64& d, u64 a, u64 b) {
    asm("fma.rn.f32x2 %0, %1, %2, %3;" : "=l"(d) : "l"(a), "l"(b), "l"(d));
}

// ---------------------------------------------------------------------------
// 1) upflow: transposed conv, stride 2, k=4, depthwise (2 groups), pad 2
// ---------------------------------------------------------------------------
__global__ void upflow_kernel(const float* __restrict__ flow,
                              const float* __restrict__ wu) {
    int idx = blockIdx.x * blockDim.x + threadIdx.x;
    if (idx >= BB*2*HWSZ) return;
    int ox = idx & 127;
    int oy = (idx >> 7) & 127;
    int ch = (idx >> 14) & 1;
    int b  = idx >> 15;
    float acc = 0.f;
    #pragma unroll
    for (int ky = 0; ky < 4; ky++) {
        int jy = oy + ky - 2;
        if (jy < 0 || jy > 126 || (jy & 1)) continue;
        int iy = jy >> 1;
        #pragma unroll
        for (int kx = 0; kx < 4; kx++) {
            int jx = ox + kx - 2;
            if (jx < 0 || jx > 126 || (jx & 1)) continue;
            int ix = jx >> 1;
            acc += wu[ch*16 + (3-ky)*4 + (3-kx)] *
                   flow[((b*2 + ch)*64 + iy)*64 + ix];
        }
    }
    g_flow[idx] = acc;
}

// ---------------------------------------------------------------------------
// 2) backward warp with zero padding + validity mask
// ---------------------------------------------------------------------------
__global__ void warp_kernel(const float* __restrict__ feat) {
    int idx = blockIdx.x * blockDim.x + threadIdx.x;
    if (idx >= BB*HWSZ) return;
    int x = idx & 127;
    int y = (idx >> 7) & 127;
    int b = idx >> 14;

    float fx = 2.5f * g_flow[(b*2 + 0)*HWSZ + y*WW + x];
    float fy = 2.5f * g_flow[(b*2 + 1)*HWSZ + y*WW + x];
    float sx = (float)x + fx;
    float sy = (float)y + fy;
    float x0f = floorf(sx), y0f = floorf(sy);
    float x1f = x0f + 1.f, y1f = y0f + 1.f;

    float wa = (x1f - sx) * (y1f - sy);
    float wb = (sx - x0f) * (y1f - sy);
    float wc = (x1f - sx) * (sy - y0f);
    float wd = (sx - x0f) * (sy - y0f);

    bool vx0 = (x0f >= 0.f) && (x0f <= 127.f);
    bool vx1 = (x1f >= 0.f) && (x1f <= 127.f);
    bool vy0 = (y0f >= 0.f) && (y0f <= 127.f);
    bool vy1 = (y1f >= 0.f) && (y1f <= 127.f);

    float ma = (vx0 && vy0) ? wa : 0.f;
    float mb = (vx1 && vy0) ? wb : 0.f;
    float mc = (vx0 && vy1) ? wc : 0.f;
    float md = (vx1 && vy1) ? wd : 0.f;
    float maskval = ma + mb + mc + md;

    int ix0 = min(max((int)x0f, 0), 127);
    int ix1 = min(max((int)x1f, 0), 127);
    int iy0 = min(max((int)y0f, 0), 127);
    int iy1 = min(max((int)y1f, 0), 127);

    int base = b * CC * HWSZ;
    int po = y*WW + x;
    if (maskval > 0.999f) {
        int oa = iy0*WW + ix0, ob = iy0*WW + ix1;
        int oc = iy1*WW + ix0, od = iy1*WW + ix1;
        for (int c = 0; c < CC; c++) {
            const float* img = feat + base + c*HWSZ;
            float v = ma*img[oa] + mb*img[ob] + mc*img[oc] + md*img[od];
            g_feat2[base + c*HWSZ + po] = v;
        }
    } else {
        for (int c = 0; c < CC; c++)
            g_feat2[base + c*HWSZ + po] = 0.f;
    }
}

// ---------------------------------------------------------------------------
// 3) correlation (49 displacements, mean over 96 ch) + lrelu
// ---------------------------------------------------------------------------
__global__ __launch_bounds__(256)
void corr_kernel(const float* __restrict__ first) {
    __shared__ float sS[22][24];
    int tx = threadIdx.x, ty = threadIdx.y;
    int x0 = blockIdx.x * 16, y0 = blockIdx.y * 16;
    int b  = blockIdx.z;
    int x = x0 + tx, y = y0 + ty;
    int tid = ty*16 + tx;

    float acc[49];
    #pragma unroll
    for (int d = 0; d < 49; d++) acc[d] = 0.f;

    for (int c = 0; c < CC; c++) {
        const float* sp = g_feat2 + (b*CC + c)*HWSZ;
        for (int i = tid; i < 22*22; i += 256) {
            int r = i / 22, cc2 = i % 22;
            int yy = y0 - 3 + r, xx = x0 - 3 + cc2;
            float v = 0.f;
            if (yy >= 0 && yy < HH && xx >= 0 && xx < WW) v = sp[yy*WW + xx];
            sS[r][cc2] = v;
        }
        __syncthreads();
        float f = first[(b*CC + c)*HWSZ + y*WW + x];
        #pragma unroll
        for (int dy = 0; dy < 7; dy++)
            #pragma unroll
            for (int dx = 0; dx < 7; dx++)
                acc[dy*7 + dx] += f * sS[ty + dy][tx + dx];
        __syncthreads();
    }
    const float inv = 1.f / 96.f;
    #pragma unroll
    for (int d = 0; d < 49; d++)
        g_corr[(b*49 + d)*HWSZ + y*WW + x] = lrelu_f(acc[d] * inv);
}

// ---------------------------------------------------------------------------
// 4) direct conv v4: 32x32 tile, block (8,32), thread = 4 consecutive x px
//    x OCB oc. Packed f32x2 accumulation (FFMA2): oc-paired accumulators,
//    weight pairs straight from float4 smem loads, value splats via mov.b64.
//    Weights fully pre-staged transposed [ic][tap][oc]; input double-buffered.
// ---------------------------------------------------------------------------
template<int IC, int OC, int OCB, int K, int PAD, bool RELU, bool ADDFLOW>
__global__ __launch_bounds__(256, 4)
void conv_kernel(const float* __restrict__ in, const float* __restrict__ wt,
                 const float* __restrict__ bias, float* __restrict__ out) {
    constexpr int TX = 32, TY = 32;
    constexpr int TSX = TX + 2*PAD;
    constexpr int TSY = TY + 2*PAD;
    constexpr int TSXP = (TSX + 3) & ~3;      // 16B-aligned row stride
    constexpr int NEL  = TSY * TSX;
    constexpr int NITER = (NEL + 255) / 256;
    constexpr int STEP_R = 256 / TSX;
    constexpr int STEP_C = 256 - STEP_R * TSX;
    constexpr int NO2 = OCB / 2;

    __shared__ float sW[IC * K * K * OCB];
    __shared__ float sIn[2][TSY][TSXP];

    const int tx = threadIdx.x;   // 0..7  (x-quad)
    const int ty = threadIdx.y;   // 0..31 (y row)
    const int tid = ty*8 + tx;
    const int x0 = blockIdx.x * TX, y0 = blockIdx.y * TY;
    const int zc = blockIdx.z;
    const int ocg = zc % (OC / OCB);
    const int b   = zc / (OC / OCB);
    const int oc0 = ocg * OCB;

    // stage all weights for this oc-group, transposed: sW[(ic*K*K + t)*OCB + o]
    for (int i = tid; i < IC*K*K*OCB; i += 256) {
        int o   = i % OCB;
        int rst = i / OCB;
        int t   = rst % (K*K);
        int ic  = rst / (K*K);
        sW[i] = wt[((oc0 + o)*IC + ic)*(K*K) + t];
    }

    // incremental (r,c) staging — no divisions in the hot path
    const int r0 = tid / TSX;
    const int c0 = tid - r0 * TSX;
    auto stage = [&](int ic, int p) {
        const float* ip = in + (b*IC + ic)*HWSZ;
        int r = r0, c = c0;
        #pragma unroll
        for (int it = 0; it < NITER; it++) {
            if (it*256 + tid < NEL) {
                int yy = y0 - PAD + r, xx = x0 - PAD + c;
                sIn[p][r][c] = (yy >= 0 && yy < HH && xx >= 0 && xx < WW)
                               ? ip[yy*WW + xx] : 0.f;
            }
            c += STEP_C; r += STEP_R;
            if (c >= TSX) { c -= TSX; r += 1; }
        }
    };

    stage(0, 0);
    __syncthreads();

    u64 acc2[NO2][4];
    #pragma unroll
    for (int o2 = 0; o2 < NO2; o2++)
        #pragma unroll
        for (int i = 0; i < 4; i++) acc2[o2][i] = 0ull;

    for (int ic = 0; ic < IC; ic++) {
        const int p = ic & 1;
        if (ic + 1 < IC) stage(ic + 1, p ^ 1);

        const float* wp = sW + ic*(K*K*OCB);
        #pragma unroll
        for (int ky = 0; ky < K; ky++) {
            const float* rowp = &sIn[p][ty + ky][tx*4];
            float4 Af = *(const float4*)rowp;
            float4 Bf = *(const float4*)(rowp + 4);
            const float va[8] = {Af.x, Af.y, Af.z, Af.w, Bf.x, Bf.y, Bf.z, Bf.w};
            u64 va2[K + 3];
            #pragma unroll
            for (int j = 0; j < K + 3; j++) va2[j] = splat2(va[j]);

            #pragma unroll
            for (int kx = 0; kx < K; kx++) {
                const float* wq = wp + (ky*K + kx)*OCB;
                u64 w2[NO2];
                if constexpr (OCB == 8) {
                    float4 wa = ((const float4*)wq)[0];
                    float4 wb = ((const float4*)wq)[1];
                    w2[0] = pack2(wa.x, wa.y); w2[1] = pack2(wa.z, wa.w);
                    w2[2] = pack2(wb.x, wb.y); w2[3] = pack2(wb.z, wb.w);
                } else {
                    #pragma unroll
                    for (int o2 = 0; o2 < NO2; o2++) {
                        float2 wf = ((const float2*)wq)[o2];
                        w2[o2] = pack2(wf.x, wf.y);
                    }
                }
                #pragma unroll
                for (int o2 = 0; o2 < NO2; o2++)
                    #pragma unroll
                    for (int i = 0; i < 4; i++)
                        ffma2(acc2[o2][i], va2[kx + i], w2[o2]);
            }
        }
        __syncthreads();
    }

    // epilogue: unpack oc pairs, float4 stores (x0 + tx*4 is 16B aligned)
    const int y = y0 + ty;
    const int x = x0 + tx*4;
    #pragma unroll
    for (int o2 = 0; o2 < NO2; o2++) {
        float lo[4], hi[4];
        #pragma unroll
        for (int i = 0; i < 4; i++) unpack2(acc2[o2][i], lo[i], hi[i]);
        #pragma unroll
        for (int h = 0; h < 2; h++) {
            int o = 2*o2 + h;
            float bv = bias[oc0 + o];
            float4 r4;
            r4.x = (h ? hi[0] : lo[0]) + bv;
            r4.y = (h ? hi[1] : lo[1]) + bv;
            r4.z = (h ? hi[2] : lo[2]) + bv;
            r4.w = (h ? hi[3] : lo[3]) + bv;
            if (RELU) {
                r4.x = lrelu_f(r4.x); r4.y = lrelu_f(r4.y);
                r4.z = lrelu_f(r4.z); r4.w = lrelu_f(r4.w);
            }
            if (ADDFLOW) {
                float4 f4 = *(const float4*)&g_flow[(b*2 + oc0 + o)*HWSZ + y*WW + x];
                r4.x += f4.x; r4.y += f4.y; r4.z += f4.z; r4.w += f4.w;
            }
            *(float4*)&out[(b*OC + oc0 + o)*HWSZ + y*WW + x] = r4;
        }
    }
}

// ---------------------------------------------------------------------------
// launch
// ---------------------------------------------------------------------------
extern "C" void kernel_launch(void* const* d_in, const int* in_sizes, int n_in,
                              void* d_out, int out_size) {
    const float* featFirst  = (const float*)d_in[2];
    const float* featSecond = (const float*)d_in[3];
    const float* tensorFlow = (const float*)d_in[4];
    const float* wu = (const float*)d_in[5];
    const float* w1 = (const float*)d_in[6];
    const float* b1 = (const float*)d_in[7];
    const float* w2 = (const float*)d_in[8];
    const float* b2 = (const float*)d_in[9];
    const float* w3 = (const float*)d_in[10];
    const float* b3 = (const float*)d_in[11];
    const float* w4 = (const float*)d_in[12];
    const float* b4 = (const float*)d_in[13];
    float* out = (float*)d_out;

    float *gflow, *gfeat2, *gcorr, *gx1, *gx2, *gx3;
    cudaGetSymbolAddress((void**)&gflow,  g_flow);
    cudaGetSymbolAddress((void**)&gfeat2, g_feat2);
    cudaGetSymbolAddress((void**)&gcorr,  g_corr);
    cudaGetSymbolAddress((void**)&gx1,    g_x1);
    cudaGetSymbolAddress((void**)&gx2,    g_x2);
    cudaGetSymbolAddress((void**)&gx3,    g_x3);

    upflow_kernel<<<(BB*2*HWSZ + 255)/256, 256>>>(tensorFlow, wu);
    warp_kernel<<<(BB*HWSZ + 255)/256, 256>>>(featSecond);
    corr_kernel<<<dim3(WW/16, HH/16, BB), dim3(16,16)>>>(featFirst);

    conv_kernel<49, 128, 8, 3, 1, true,  false>
        <<<dim3(WW/32, HH/32, BB*(128/8)), dim3(8,32)>>>(gcorr, w1, b1, gx1);
    conv_kernel<128, 64, 8, 3, 1, true,  false>
        <<<dim3(WW/32, HH/32, BB*(64/8)),  dim3(8,32)>>>(gx1, w2, b2, gx2);
    conv_kernel<64,  32, 8, 3, 1, true,  false>
        <<<dim3(WW/32, HH/32, BB*(32/8)),  dim3(8,32)>>>(gx2, w3, b3, gx3);
    conv_kernel<32,   2, 2, 5, 2, false, true>
        <<<dim3(WW/32, HH/32, BB*(2/2)),   dim3(8,32)>>>(gx3, w4, b4, out);
}

// round 7
// speedup vs baseline: 1.6600x; 1.6600x over previous
#include <cuda_runtime.h>
#include <cuda_fp16.h>
#include <cstdint>

// Problem constants
#define BB 16
#define CC 96
#define HH 128
#define WW 128
#define HWSZ (HH*WW)

// Scratch (allocation-guard-safe: __device__ globals)
__device__ float g_flow [BB*2  *HWSZ];
__device__ float g_feat2[BB*CC *HWSZ];
__device__ float g_corr [BB*49 *HWSZ];
__device__ float g_x1   [BB*128*HWSZ];
__device__ float g_x2   [BB*64 *HWSZ];
__device__ float g_x3   [BB*32 *HWSZ];

__device__ __forceinline__ float lrelu_f(float x) { return x >= 0.f ? x : 0.1f * x; }

// m16n8k16 fp16 MMA, fp32 accumulate (arch-agnostic PTX, sm_80+)
__device__ __forceinline__ void hmma16816(float* d,
        uint32_t a0, uint32_t a1, uint32_t a2, uint32_t a3,
        uint32_t b0, uint32_t b1) {
    asm volatile(
        "mma.sync.aligned.m16n8k16.row.col.f32.f16.f16.f32 "
        "{%0,%1,%2,%3}, {%4,%5,%6,%7}, {%8,%9}, {%0,%1,%2,%3};"
        : "+f"(d[0]), "+f"(d[1]), "+f"(d[2]), "+f"(d[3])
        : "r"(a0), "r"(a1), "r"(a2), "r"(a3), "r"(b0), "r"(b1));
}

// ---------------------------------------------------------------------------
// 1) upflow
// ---------------------------------------------------------------------------
__global__ void upflow_kernel(const float* __restrict__ flow,
                              const float* __restrict__ wu) {
    int idx = blockIdx.x * blockDim.x + threadIdx.x;
    if (idx >= BB*2*HWSZ) return;
    int ox = idx & 127;
    int oy = (idx >> 7) & 127;
    int ch = (idx >> 14) & 1;
    int b  = idx >> 15;
    float acc = 0.f;
    #pragma unroll
    for (int ky = 0; ky < 4; ky++) {
        int jy = oy + ky - 2;
        if (jy < 0 || jy > 126 || (jy & 1)) continue;
        int iy = jy >> 1;
        #pragma unroll
        for (int kx = 0; kx < 4; kx++) {
            int jx = ox + kx - 2;
            if (jx < 0 || jx > 126 || (jx & 1)) continue;
            int ix = jx >> 1;
            acc += wu[ch*16 + (3-ky)*4 + (3-kx)] *
                   flow[((b*2 + ch)*64 + iy)*64 + ix];
        }
    }
    g_flow[idx] = acc;
}

// ---------------------------------------------------------------------------
// 2) backward warp
// ---------------------------------------------------------------------------
__global__ void warp_kernel(const float* __restrict__ feat) {
    int idx = blockIdx.x * blockDim.x + threadIdx.x;
    if (idx >= BB*HWSZ) return;
    int x = idx & 127;
    int y = (idx >> 7) & 127;
    int b = idx >> 14;

    float fx = 2.5f * g_flow[(b*2 + 0)*HWSZ + y*WW + x];
    float fy = 2.5f * g_flow[(b*2 + 1)*HWSZ + y*WW + x];
    float sx = (float)x + fx;
    float sy = (float)y + fy;
    float x0f = floorf(sx), y0f = floorf(sy);
    float x1f = x0f + 1.f, y1f = y0f + 1.f;

    float wa = (x1f - sx) * (y1f - sy);
    float wb = (sx - x0f) * (y1f - sy);
    float wc = (x1f - sx) * (sy - y0f);
    float wd = (sx - x0f) * (sy - y0f);

    bool vx0 = (x0f >= 0.f) && (x0f <= 127.f);
    bool vx1 = (x1f >= 0.f) && (x1f <= 127.f);
    bool vy0 = (y0f >= 0.f) && (y0f <= 127.f);
    bool vy1 = (y1f >= 0.f) && (y1f <= 127.f);

    float ma = (vx0 && vy0) ? wa : 0.f;
    float mb = (vx1 && vy0) ? wb : 0.f;
    float mc = (vx0 && vy1) ? wc : 0.f;
    float md = (vx1 && vy1) ? wd : 0.f;
    float maskval = ma + mb + mc + md;

    int ix0 = min(max((int)x0f, 0), 127);
    int ix1 = min(max((int)x1f, 0), 127);
    int iy0 = min(max((int)y0f, 0), 127);
    int iy1 = min(max((int)y1f, 0), 127);

    int base = b * CC * HWSZ;
    int po = y*WW + x;
    if (maskval > 0.999f) {
        int oa = iy0*WW + ix0, ob = iy0*WW + ix1;
        int oc = iy1*WW + ix0, od = iy1*WW + ix1;
        for (int c = 0; c < CC; c++) {
            const float* img = feat + base + c*HWSZ;
            float v = ma*img[oa] + mb*img[ob] + mc*img[oc] + md*img[od];
            g_feat2[base + c*HWSZ + po] = v;
        }
    } else {
        for (int c = 0; c < CC; c++)
            g_feat2[base + c*HWSZ + po] = 0.f;
    }
}

// ---------------------------------------------------------------------------
// 3) correlation + lrelu
// ---------------------------------------------------------------------------
__global__ __launch_bounds__(256)
void corr_kernel(const float* __restrict__ first) {
    __shared__ float sS[22][24];
    int tx = threadIdx.x, ty = threadIdx.y;
    int x0 = blockIdx.x * 16, y0 = blockIdx.y * 16;
    int b  = blockIdx.z;
    int x = x0 + tx, y = y0 + ty;
    int tid = ty*16 + tx;

    float acc[49];
    #pragma unroll
    for (int d = 0; d < 49; d++) acc[d] = 0.f;

    for (int c = 0; c < CC; c++) {
        const float* sp = g_feat2 + (b*CC + c)*HWSZ;
        for (int i = tid; i < 22*22; i += 256) {
            int r = i / 22, cc2 = i % 22;
            int yy = y0 - 3 + r, xx = x0 - 3 + cc2;
            float v = 0.f;
            if (yy >= 0 && yy < HH && xx >= 0 && xx < WW) v = sp[yy*WW + xx];
            sS[r][cc2] = v;
        }
        __syncthreads();
        float f = first[(b*CC + c)*HWSZ + y*WW + x];
        #pragma unroll
        for (int dy = 0; dy < 7; dy++)
            #pragma unroll
            for (int dx = 0; dx < 7; dx++)
                acc[dy*7 + dx] += f * sS[ty + dy][tx + dx];
        __syncthreads();
    }
    const float inv = 1.f / 96.f;
    #pragma unroll
    for (int d = 0; d < 49; d++)
        g_corr[(b*49 + d)*HWSZ + y*WW + x] = lrelu_f(acc[d] * inv);
}

// ---------------------------------------------------------------------------
// 4) HMMA fp16 implicit-GEMM 3x3 conv (pad=1), fp32 accumulate.
//    CTA = (image row y, batch b). GEMM: M=128 (x), N=OC, K=9*IC (im2col in K).
//    K chunks of 64 staged to smem as fp16; 8 warps x 16 M-rows;
//    mma.sync m16n8k16, fragments via plain LDS.32 (PTX-ISA layouts).
// ---------------------------------------------------------------------------
template<int IC, int OC>
__global__ __launch_bounds__(256)
void conv_hmma_kernel(const float* __restrict__ in, const float* __restrict__ wt,
                      const float* __restrict__ bias, float* __restrict__ out) {
    constexpr int KK9 = 9 * IC;
    constexpr int NCH = (KK9 + 63) / 64;
    constexpr int NB  = OC / 8;
    constexpr int AP  = 74;                 // padded row length (halves)

    __shared__ __half sA[128 * AP];
    __shared__ __half sB[OC  * AP];

    const int tid = threadIdx.x;
    const int w = tid >> 5, l = tid & 31;
    const int y = blockIdx.x, b = blockIdx.y;
    const int mw = w * 16;
    const int r = l >> 2, c = l & 3;

    float d[NB][4];
    #pragma unroll
    for (int nb = 0; nb < NB; nb++)
        #pragma unroll
        for (int i = 0; i < 4; i++) d[nb][i] = 0.f;

    const int mA = tid & 127;      // pixel x for A staging (coalesced LDG)
    const int k0 = tid >> 7;       // 0..1

    for (int ch = 0; ch < NCH; ch++) {
        __syncthreads();           // writers vs previous chunk's readers
        // ---- stage A: 128(m) x 64(k) fp16 ----
        #pragma unroll
        for (int it = 0; it < 32; it++) {
            const int kslot = k0 + it*2;
            const int kg = ch*64 + kslot;
            float v = 0.f;
            if (kg < KK9) {
                const int tap = kg / IC;
                const int ic  = kg - tap*IC;
                const int ky  = tap / 3;
                const int kx  = tap - ky*3;
                const int yy  = y + ky - 1;
                const int xx  = mA + kx - 1;
                if ((unsigned)yy < (unsigned)HH && (unsigned)xx < (unsigned)WW)
                    v = in[((b*IC + ic)*HH + yy)*WW + xx];
            }
            sA[mA*AP + kslot] = __float2half_rn(v);
        }
        // ---- stage B: OC(n) x 64(k) fp16, B[n][k] = w[n][ic][tap] ----
        for (int i = tid; i < OC*64; i += 256) {
            const int n = i >> 6, kslot = i & 63;
            const int kg = ch*64 + kslot;
            float v = 0.f;
            if (kg < KK9) {
                const int tap = kg / IC;
                const int ic  = kg - tap*IC;
                v = wt[(n*IC + ic)*9 + tap];
            }
            sB[n*AP + kslot] = __float2half_rn(v);
        }
        __syncthreads();

        // ---- compute: 4 k-steps of 16 ----
        #pragma unroll
        for (int ks = 0; ks < 4; ks++) {
            const int kb = ks*16 + 2*c;
            uint32_t a0 = *(const uint32_t*)&sA[(mw + r    )*AP + kb];
            uint32_t a1 = *(const uint32_t*)&sA[(mw + r + 8)*AP + kb];
            uint32_t a2 = *(const uint32_t*)&sA[(mw + r    )*AP + kb + 8];
            uint32_t a3 = *(const uint32_t*)&sA[(mw + r + 8)*AP + kb + 8];
            #pragma unroll
            for (int nb = 0; nb < NB; nb++) {
                const int n = nb*8 + r;
                uint32_t b0 = *(const uint32_t*)&sB[n*AP + kb];
                uint32_t b1 = *(const uint32_t*)&sB[n*AP + kb + 8];
                hmma16816(d[nb], a0, a1, a2, a3, b0, b1);
            }
        }
    }

    // ---- epilogue: bias + lrelu, scatter to NCHW ----
    const int x0 = mw + r;
    #pragma unroll
    for (int nb = 0; nb < NB; nb++) {
        const int oc0 = nb*8 + 2*c;
        const float bv0 = bias[oc0], bv1 = bias[oc0 + 1];
        float v;
        v = lrelu_f(d[nb][0] + bv0);
        out[((b*OC + oc0    )*HH + y)*WW + x0    ] = v;
        v = lrelu_f(d[nb][1] + bv1);
        out[((b*OC + oc0 + 1)*HH + y)*WW + x0    ] = v;
        v = lrelu_f(d[nb][2] + bv0);
        out[((b*OC + oc0    )*HH + y)*WW + x0 + 8] = v;
        v = lrelu_f(d[nb][3] + bv1);
        out[((b*OC + oc0 + 1)*HH + y)*WW + x0 + 8] = v;
    }
}

// ---------------------------------------------------------------------------
// 5) fp32 direct conv (conv4: 5x5, IC=32, OC=2, no relu, +flow residual)
// ---------------------------------------------------------------------------
template<int IC, int OC, int OCB, int K, int PAD, bool RELU, bool ADDFLOW>
__global__ __launch_bounds__(256, 4)
void conv_kernel(const float* __restrict__ in, const float* __restrict__ wt,
                 const float* __restrict__ bias, float* __restrict__ out) {
    constexpr int TX = 32, TY = 32;
    constexpr int TSX = TX + 2*PAD;
    constexpr int TSY = TY + 2*PAD;
    constexpr int TSXP = (TSX + 3) & ~3;

    __shared__ float sW[IC * K * K * OCB];
    __shared__ float sIn[2][TSY][TSXP];

    const int tx = threadIdx.x;
    const int ty = threadIdx.y;
    const int tid = ty*8 + tx;
    const int x0 = blockIdx.x * TX, y0 = blockIdx.y * TY;
    const int zc = blockIdx.z;
    const int ocg = zc % (OC / OCB);
    const int b   = zc / (OC / OCB);
    const int oc0 = ocg * OCB;

    for (int i = tid; i < IC*K*K*OCB; i += 256) {
        int o   = i % OCB;
        int rst = i / OCB;
        int t   = rst % (K*K);
        int ic  = rst / (K*K);
        sW[i] = wt[((oc0 + o)*IC + ic)*(K*K) + t];
    }

    auto stage = [&](int ic, int p) {
        const float* ip = in + (b*IC + ic)*HWSZ;
        for (int i = tid; i < TSY*TSX; i += 256) {
            int r  = i / TSX;
            int c  = i - r*TSX;
            int yy = y0 - PAD + r, xx = x0 - PAD + c;
            sIn[p][r][c] = (yy >= 0 && yy < HH && xx >= 0 && xx < WW)
                           ? ip[yy*WW + xx] : 0.f;
        }
    };

    stage(0, 0);
    __syncthreads();

    float acc[OCB][4];
    #pragma unroll
    for (int o = 0; o < OCB; o++)
        #pragma unroll
        for (int i = 0; i < 4; i++) acc[o][i] = 0.f;

    for (int ic = 0; ic < IC; ic++) {
        const int p = ic & 1;
        if (ic + 1 < IC) stage(ic + 1, p ^ 1);

        const float* wp = sW + ic*(K*K*OCB);
        #pragma unroll
        for (int ky = 0; ky < K; ky++) {
            const float* rowp = &sIn[p][ty + ky][tx*4];
            float4 Af = *(const float4*)rowp;
            float4 Bf = *(const float4*)(rowp + 4);
            float va[8] = {Af.x, Af.y, Af.z, Af.w, Bf.x, Bf.y, Bf.z, Bf.w};
            #pragma unroll
            for (int kx = 0; kx < K; kx++) {
                const float* wq = wp + (ky*K + kx)*OCB;
                #pragma unroll
                for (int o = 0; o < OCB; o++) {
                    float wv = wq[o];
                    #pragma unroll
                    for (int i = 0; i < 4; i++)
                        acc[o][i] = fmaf(va[i + kx], wv, acc[o][i]);
                }
            }
        }
        __syncthreads();
    }

    const int y = y0 + ty;
    const int x = x0 + tx*4;
    #pragma unroll
    for (int o = 0; o < OCB; o++) {
        float bv = bias[oc0 + o];
        float4 r4;
        r4.x = acc[o][0] + bv; r4.y = acc[o][1] + bv;
        r4.z = acc[o][2] + bv; r4.w = acc[o][3] + bv;
        if (RELU) {
            r4.x = lrelu_f(r4.x); r4.y = lrelu_f(r4.y);
            r4.z = lrelu_f(r4.z); r4.w = lrelu_f(r4.w);
        }
        if (ADDFLOW) {
            float4 f4 = *(const float4*)&g_flow[(b*2 + oc0 + o)*HWSZ + y*WW + x];
            r4.x += f4.x; r4.y += f4.y; r4.z += f4.z; r4.w += f4.w;
        }
        *(float4*)&out[(b*OC + oc0 + o)*HWSZ + y*WW + x] = r4;
    }
}

// ---------------------------------------------------------------------------
// launch
// ---------------------------------------------------------------------------
extern "C" void kernel_launch(void* const* d_in, const int* in_sizes, int n_in,
                              void* d_out, int out_size) {
    const float* featFirst  = (const float*)d_in[2];
    const float* featSecond = (const float*)d_in[3];
    const float* tensorFlow = (const float*)d_in[4];
    const float* wu = (const float*)d_in[5];
    const float* w1 = (const float*)d_in[6];
    const float* b1 = (const float*)d_in[7];
    const float* w2 = (const float*)d_in[8];
    const float* b2 = (const float*)d_in[9];
    const float* w3 = (const float*)d_in[10];
    const float* b3 = (const float*)d_in[11];
    const float* w4 = (const float*)d_in[12];
    const float* b4 = (const float*)d_in[13];
    float* out = (float*)d_out;

    float *gflow, *gfeat2, *gcorr, *gx1, *gx2, *gx3;
    cudaGetSymbolAddress((void**)&gflow,  g_flow);
    cudaGetSymbolAddress((void**)&gfeat2, g_feat2);
    cudaGetSymbolAddress((void**)&gcorr,  g_corr);
    cudaGetSymbolAddress((void**)&gx1,    g_x1);
    cudaGetSymbolAddress((void**)&gx2,    g_x2);
    cudaGetSymbolAddress((void**)&gx3,    g_x3);

    upflow_kernel<<<(BB*2*HWSZ + 255)/256, 256>>>(tensorFlow, wu);
    warp_kernel<<<(BB*HWSZ + 255)/256, 256>>>(featSecond);
    corr_kernel<<<dim3(WW/16, HH/16, BB), dim3(16,16)>>>(featFirst);

    conv_hmma_kernel<49, 128><<<dim3(HH, BB), 256>>>(gcorr, w1, b1, gx1);
    conv_hmma_kernel<128, 64><<<dim3(HH, BB), 256>>>(gx1,  w2, b2, gx2);
    conv_hmma_kernel<64,  32><<<dim3(HH, BB), 256>>>(gx2,  w3, b3, gx3);

    conv_kernel<32, 2, 2, 5, 2, false, true>
        <<<dim3(WW/32, HH/32, BB), dim3(8,32)>>>(gx3, w4, b4, out);
}